// round 6
// baseline (speedup 1.0000x reference)
#include <cuda_runtime.h>
#include <cstdint>

#define Nn   100000
#define Ee   1000000
#define FIN  128
#define HID  64
#define OUTF 40
#define NL   4
#define ALPHAc 0.5f
#define EPSBN  1e-5f

#define NB_SCAN ((Nn + 255) / 256)   // 391

// ---------------- scratch ----------------------------------------------------
__device__ __align__(16) float g_h0[Nn * HID];
__device__ __align__(16) float g_hprev[Nn * HID];
__device__ __align__(16) float g_support[Nn * HID];
__device__ __align__(16) float g_agg[Nn * HID];
__device__ float g_dinv[Nn];
__device__ float g_stats[2][2 * HID];
__device__ int   g_is64;
__device__ int   g_cnt[Nn];
__device__ int   g_bsum[NB_SCAN];
__device__ int   g_boff[NB_SCAN];
__device__ int   g_rowptr[Nn + 1];
__device__ int   g_cur[Nn];
__device__ __align__(8) int2 g_eidx[Ee];

// ---------------- edge index access -------------------------------------------
__device__ __forceinline__ int edge_at(const void* ei, int is64, int idx) {
    if (is64) return (int)((const long long*)ei)[idx];
    return ((const int*)ei)[idx];
}

__global__ void k_detect_zero(const void* ei) {
    int i = blockIdx.x * blockDim.x + threadIdx.x;
    if (i == 0) {
        const long long* p = (const long long*)ei;
        int ok = 1;
        for (int j = 0; j < 8; j++) {
            long long v = p[j];
            if (v < 0 || v >= Nn) ok = 0;
        }
        g_is64 = ok;
    }
    if (i < 4 * HID) ((float*)g_stats)[i] = 0.0f;
    if (i < Nn) g_cnt[i] = 0;
}

__global__ void k_deg(const void* ei) {
    int e = blockIdx.x * blockDim.x + threadIdx.x;
    if (e < Ee) {
        int c = edge_at(ei, g_is64, Ee + e);
        atomicAdd(&g_cnt[c], 1);
    }
}

__global__ void k_bsum() {
    __shared__ int s[256];
    int t = threadIdx.x;
    int i = blockIdx.x * 256 + t;
    s[t] = (i < Nn) ? g_cnt[i] : 0;
    __syncthreads();
    for (int st = 128; st > 0; st >>= 1) {
        if (t < st) s[t] += s[t + st];
        __syncthreads();
    }
    if (t == 0) g_bsum[blockIdx.x] = s[0];
}

__global__ void k_bscan() {
    __shared__ int s[512];
    int t = threadIdx.x;
    int orig = (t < NB_SCAN) ? g_bsum[t] : 0;
    s[t] = orig;
    __syncthreads();
    for (int off = 1; off < 512; off <<= 1) {
        int v = (t >= off) ? s[t - off] : 0;
        __syncthreads();
        s[t] += v;
        __syncthreads();
    }
    if (t < NB_SCAN) g_boff[t] = s[t] - orig;
}

__global__ void k_rowptr() {
    __shared__ int s[256];
    int t = threadIdx.x;
    int i = blockIdx.x * 256 + t;
    int orig = (i < Nn) ? g_cnt[i] : 0;
    s[t] = orig;
    __syncthreads();
    for (int off = 1; off < 256; off <<= 1) {
        int v = (t >= off) ? s[t - off] : 0;
        __syncthreads();
        s[t] += v;
        __syncthreads();
    }
    if (i < Nn) {
        int rp = g_boff[blockIdx.x] + s[t] - orig;
        g_rowptr[i] = rp;
        g_cur[i] = rp;
        g_dinv[i] = rsqrtf((float)orig + 1.0f);
    }
    if (i == 0) g_rowptr[Nn] = Ee;
}

__global__ void k_fill(const void* __restrict__ ei) {
    int e = blockIdx.x * blockDim.x + threadIdx.x;
    if (e < Ee) {
        int is64 = g_is64;
        int r = edge_at(ei, is64, e);
        int c = edge_at(ei, is64, Ee + e);
        float w = g_dinv[r] * g_dinv[c];
        int pos = atomicAdd(&g_cur[c], 1);
        g_eidx[pos] = make_int2(r * HID, __float_as_int(w));
    }
}

// ---------------- input GEMM: h = relu(x @ Wi + bi), float4 LDS --------------
__global__ __launch_bounds__(256) void k_ingemm(const float* __restrict__ x,
                                                const float* __restrict__ Wi,
                                                const float* __restrict__ bi) {
    __shared__ float Wt[HID][FIN + 4];   // transposed, padded (132)
    __shared__ float bs[HID];
    __shared__ float xs[16][FIN];
    int tid = threadIdx.x;
    for (int i = tid; i < FIN * HID; i += 256) {
        int k = i >> 6, f = i & 63;
        Wt[f][k] = Wi[i];
    }
    if (tid < HID) bs[tid] = bi[tid];
    __syncthreads();
    int f = tid & 63, g = tid >> 6;
    const int ntiles = Nn / 16;
    for (int tile = blockIdx.x; tile < ntiles; tile += gridDim.x) {
        int rowBase = tile * 16;
        for (int i = tid; i < 16 * 32; i += 256) {
            int rr = i >> 5, q = (i & 31) * 4;
            *(float4*)(&xs[rr][q]) = *(const float4*)(x + (rowBase + rr) * FIN + q);
        }
        __syncthreads();
        float acc[4];
        #pragma unroll
        for (int i = 0; i < 4; i++) acc[i] = bs[f];
        #pragma unroll 8
        for (int k0 = 0; k0 < FIN; k0 += 4) {
            float4 wv = *(const float4*)(&Wt[f][k0]);
            #pragma unroll
            for (int i = 0; i < 4; i++) {
                float4 xv = *(const float4*)(&xs[g * 4 + i][k0]);
                acc[i] = fmaf(xv.x, wv.x, acc[i]);
                acc[i] = fmaf(xv.y, wv.y, acc[i]);
                acc[i] = fmaf(xv.z, wv.z, acc[i]);
                acc[i] = fmaf(xv.w, wv.w, acc[i]);
            }
        }
        #pragma unroll
        for (int i = 0; i < 4; i++) {
            int gr = rowBase + g * 4 + i;
            float h = fmaxf(acc[i], 0.0f);
            g_h0[gr * HID + f] = h;
            g_hprev[gr * HID + f] = h;
        }
        __syncthreads();
    }
}

// ------- layer GEMM: support = hp@(I+W1); agg = h0@(aI+W2) + d^2*support ----
// hp = (apply) ? hprev + relu(BN(agg_prev)) : hprev   (written back to g_hprev)
__global__ __launch_bounds__(256) void k_layergemm(const float* __restrict__ W1,
                                                   const float* __restrict__ W2,
                                                   const float* __restrict__ gamma,
                                                   const float* __restrict__ beta,
                                                   int apply, int rb, int zb) {
    __shared__ float W1t[HID][HID + 4];  // transposed+diag, padded (68)
    __shared__ float W2t[HID][HID + 4];
    __shared__ float hp[16][HID];
    __shared__ float h0s[16][HID];
    __shared__ __align__(16) float scs[HID];
    __shared__ __align__(16) float shs[HID];
    int tid = threadIdx.x;
    if (blockIdx.x == 0 && tid < 2 * HID) g_stats[zb][tid] = 0.0f;
    for (int i = tid; i < HID * HID; i += 256) {
        int k = i >> 6, f = i & 63;
        float dg = (k == f) ? 1.0f : 0.0f;
        W1t[f][k] = W1[i] + dg;
        W2t[f][k] = W2[i] + dg * ALPHAc;
    }
    if (tid < HID) {
        if (apply) {
            float m = g_stats[rb][tid] * (1.0f / Nn);
            float v = g_stats[rb][HID + tid] * (1.0f / Nn) - m * m;
            float inv = rsqrtf(v + EPSBN);
            float scale = gamma[tid] * inv;
            scs[tid] = scale;
            shs[tid] = beta[tid] - m * scale;
        } else {
            scs[tid] = 0.0f;
            shs[tid] = 0.0f;
        }
    }
    __syncthreads();
    int f = tid & 63, g = tid >> 6;
    const int ntiles = Nn / 16;
    for (int tile = blockIdx.x; tile < ntiles; tile += gridDim.x) {
        int rowBase = tile * 16;
        if (apply) {
            for (int i = tid; i < 16 * 16; i += 256) {
                int rr = i >> 4, q = (i & 15) * 4;
                int gr = rowBase + rr;
                float4 p = *(const float4*)(g_hprev + gr * HID + q);
                float4 a = *(const float4*)(g_agg + gr * HID + q);
                float4 sc4 = *(const float4*)(&scs[q]);
                float4 sh4 = *(const float4*)(&shs[q]);
                p.x += fmaxf(fmaf(a.x, sc4.x, sh4.x), 0.0f);
                p.y += fmaxf(fmaf(a.y, sc4.y, sh4.y), 0.0f);
                p.z += fmaxf(fmaf(a.z, sc4.z, sh4.z), 0.0f);
                p.w += fmaxf(fmaf(a.w, sc4.w, sh4.w), 0.0f);
                *(float4*)(g_hprev + gr * HID + q) = p;
                *(float4*)(&hp[rr][q]) = p;
                *(float4*)(&h0s[rr][q]) = *(const float4*)(g_h0 + gr * HID + q);
            }
        } else {
            for (int i = tid; i < 16 * 16; i += 256) {
                int rr = i >> 4, q = (i & 15) * 4;
                int gr = rowBase + rr;
                *(float4*)(&hp[rr][q])  = *(const float4*)(g_hprev + gr * HID + q);
                *(float4*)(&h0s[rr][q]) = *(const float4*)(g_h0 + gr * HID + q);
            }
        }
        __syncthreads();
        float a1[4] = {0.f, 0.f, 0.f, 0.f};
        float a2[4] = {0.f, 0.f, 0.f, 0.f};
        #pragma unroll 4
        for (int k0 = 0; k0 < HID; k0 += 4) {
            float4 w1v = *(const float4*)(&W1t[f][k0]);
            float4 w2v = *(const float4*)(&W2t[f][k0]);
            #pragma unroll
            for (int i = 0; i < 4; i++) {
                float4 hv  = *(const float4*)(&hp[g * 4 + i][k0]);
                float4 h0v = *(const float4*)(&h0s[g * 4 + i][k0]);
                a1[i] = fmaf(hv.x, w1v.x, a1[i]);
                a1[i] = fmaf(hv.y, w1v.y, a1[i]);
                a1[i] = fmaf(hv.z, w1v.z, a1[i]);
                a1[i] = fmaf(hv.w, w1v.w, a1[i]);
                a2[i] = fmaf(h0v.x, w2v.x, a2[i]);
                a2[i] = fmaf(h0v.y, w2v.y, a2[i]);
                a2[i] = fmaf(h0v.z, w2v.z, a2[i]);
                a2[i] = fmaf(h0v.w, w2v.w, a2[i]);
            }
        }
        #pragma unroll
        for (int i = 0; i < 4; i++) {
            int gr = rowBase + g * 4 + i;
            float d = g_dinv[gr];
            g_support[gr * HID + f] = a1[i];
            g_agg[gr * HID + f]     = fmaf(d * d, a1[i], a2[i]);
        }
        __syncthreads();
    }
}

// ---- warp-per-node CSR gather + BN stats (self loop already in g_agg) --------
__global__ __launch_bounds__(256) void k_gather(int wb) {
    __shared__ float4 s_sum[8][16];
    __shared__ float4 s_sq[8][16];
    int tid = threadIdx.x;
    int wid = tid >> 5;
    int lane = tid & 31;
    int half = lane >> 4;
    int q = (lane & 15) * 4;
    float4 lsum = make_float4(0.f, 0.f, 0.f, 0.f);
    float4 lsq  = make_float4(0.f, 0.f, 0.f, 0.f);
    const int nwarps = gridDim.x * 8;
    for (int n = blockIdx.x * 8 + wid; n < Nn; n += nwarps) {
        float4 acc = make_float4(0.f, 0.f, 0.f, 0.f);
        if (half == 0) acc = *(const float4*)(g_agg + n * HID + q);
        int p0 = g_rowptr[n], p1 = g_rowptr[n + 1];
        #pragma unroll 2
        for (int p = p0 + half; p < p1; p += 2) {
            int2 ed = __ldg(&g_eidx[p]);
            float w = __int_as_float(ed.y);
            float4 s = __ldg((const float4*)(g_support + ed.x + q));
            acc.x = fmaf(w, s.x, acc.x);
            acc.y = fmaf(w, s.y, acc.y);
            acc.z = fmaf(w, s.z, acc.z);
            acc.w = fmaf(w, s.w, acc.w);
        }
        acc.x += __shfl_xor_sync(0xffffffffu, acc.x, 16);
        acc.y += __shfl_xor_sync(0xffffffffu, acc.y, 16);
        acc.z += __shfl_xor_sync(0xffffffffu, acc.z, 16);
        acc.w += __shfl_xor_sync(0xffffffffu, acc.w, 16);
        if (half == 0) {
            *(float4*)(g_agg + n * HID + q) = acc;
            lsum.x += acc.x; lsum.y += acc.y; lsum.z += acc.z; lsum.w += acc.w;
            lsq.x += acc.x * acc.x; lsq.y += acc.y * acc.y;
            lsq.z += acc.z * acc.z; lsq.w += acc.w * acc.w;
        }
    }
    if (half == 0) {
        s_sum[wid][lane & 15] = lsum;
        s_sq[wid][lane & 15]  = lsq;
    }
    __syncthreads();
    if (tid < 16) {
        float4 a = s_sum[0][tid], b = s_sq[0][tid];
        #pragma unroll
        for (int wv = 1; wv < 8; wv++) {
            float4 c = s_sum[wv][tid], d = s_sq[wv][tid];
            a.x += c.x; a.y += c.y; a.z += c.z; a.w += c.w;
            b.x += d.x; b.y += d.y; b.z += d.z; b.w += d.w;
        }
        float* st = g_stats[wb];
        atomicAdd(&st[tid * 4 + 0], a.x);
        atomicAdd(&st[tid * 4 + 1], a.y);
        atomicAdd(&st[tid * 4 + 2], a.z);
        atomicAdd(&st[tid * 4 + 3], a.w);
        atomicAdd(&st[HID + tid * 4 + 0], b.x);
        atomicAdd(&st[HID + tid * 4 + 1], b.y);
        atomicAdd(&st[HID + tid * 4 + 2], b.z);
        atomicAdd(&st[HID + tid * 4 + 3], b.w);
    }
}

// ---------------- output GEMM with fused final BN ------------------------------
__global__ __launch_bounds__(256) void k_outgemm(const float* __restrict__ Wo,
                                                 const float* __restrict__ bo,
                                                 const float* __restrict__ gamma,
                                                 const float* __restrict__ beta,
                                                 int rb,
                                                 float* __restrict__ out) {
    __shared__ float Ws[HID * OUTF];
    __shared__ float bs[OUTF];
    __shared__ float hp[32][HID];
    __shared__ float scs[HID];
    __shared__ float shs[HID];
    int tid = threadIdx.x;
    for (int i = tid; i < HID * OUTF; i += 256) Ws[i] = Wo[i];
    if (tid < OUTF) bs[tid] = bo[tid];
    if (tid < HID) {
        float m = g_stats[rb][tid] * (1.0f / Nn);
        float v = g_stats[rb][HID + tid] * (1.0f / Nn) - m * m;
        float inv = rsqrtf(v + EPSBN);
        float scale = gamma[tid] * inv;
        scs[tid] = scale;
        shs[tid] = beta[tid] - m * scale;
    }
    __syncthreads();
    int rowBase = blockIdx.x * 32;
    for (int i = tid; i < 32 * HID; i += 256) {
        int rr = i >> 6, f = i & 63;
        int gr = rowBase + rr;
        float hv = g_hprev[gr * HID + f]
                 + fmaxf(fmaf(g_agg[gr * HID + f], scs[f], shs[f]), 0.0f);
        hp[rr][f] = hv;
    }
    __syncthreads();
    for (int idx = tid; idx < 32 * OUTF; idx += 256) {
        int rr = idx / OUTF, f = idx % OUTF;
        int gr = rowBase + rr;
        float acc = bs[f];
        #pragma unroll
        for (int k = 0; k < HID; k++) acc += hp[rr][k] * Ws[k * OUTF + f];
        out[gr * OUTF + f] = acc;
    }
}

// ---------------- launch --------------------------------------------------------
extern "C" void kernel_launch(void* const* d_in, const int* in_sizes, int n_in,
                              void* d_out, int out_size) {
    const float* x     = (const float*)d_in[0];
    const void*  ei    = d_in[1];
    const float* Wi    = (const float*)d_in[2];
    const float* bi    = (const float*)d_in[3];
    const float* w1    = (const float*)d_in[4];
    const float* w2    = (const float*)d_in[5];
    const float* gamma = (const float*)d_in[6];
    const float* beta  = (const float*)d_in[7];
    const float* Wo    = (const float*)d_in[8];
    const float* bo    = (const float*)d_in[9];
    float* out = (float*)d_out;

    k_detect_zero<<<(Nn + 255) / 256, 256>>>(ei);
    k_deg<<<(Ee + 255) / 256, 256>>>(ei);
    k_bsum<<<NB_SCAN, 256>>>();
    k_bscan<<<1, 512>>>();
    k_rowptr<<<NB_SCAN, 256>>>();
    k_fill<<<(Ee + 255) / 256, 256>>>(ei);

    k_ingemm<<<592, 256>>>(x, Wi, bi);

    for (int l = 0; l < NL; l++) {
        int wb = l & 1;
        int rb = (l - 1) & 1;
        k_layergemm<<<592, 256>>>(w1 + l * HID * HID, w2 + l * HID * HID,
                                  gamma + (l - 1) * HID, beta + (l - 1) * HID,
                                  (l > 0) ? 1 : 0, rb, wb);
        k_gather<<<1184, 256>>>(wb);
    }

    k_outgemm<<<Nn / 32, 256>>>(Wo, bo, gamma + (NL - 1) * HID,
                                beta + (NL - 1) * HID, (NL - 1) & 1, out);
}